// round 1
// baseline (speedup 1.0000x reference)
#include <cuda_runtime.h>

#define S_    512
#define B_    64
#define I_    512
#define H_    512
#define GRID  148
#define NT    256
#define NWORK 128
#define JPB   4

// Scratch (device globals: allocation-free rule)
__device__ float    g_gx[(size_t)S_ * 4 * H_ * B_];   // [s][gate][j][b], 256 MB
__device__ float    g_h[2][H_ * B_];                  // [buf][j][b] double-buffered hidden state
__device__ unsigned g_bar_count;
__device__ unsigned g_bar_release;

// Grid-wide barrier (all GRID blocks resident: grid == SM count, 1 block/SM).
// __threadfence() (gpu scope) also emits CCTL.IVALL -> L1D invalidated, so
// cross-SM h/gx updates are never served stale from L1.
__device__ __forceinline__ void grid_barrier(unsigned& phase) {
    __syncthreads();
    if (threadIdx.x == 0) {
        __threadfence();
        unsigned ticket = atomicAdd(&g_bar_count, 1u);
        if (ticket == (unsigned)(gridDim.x - 1)) {
            g_bar_count = 0u;
            __threadfence();
            atomicAdd(&g_bar_release, 1u);
        } else {
            volatile unsigned* rel = &g_bar_release;
            while (*rel == phase) { }
        }
        __threadfence();
        phase += 1u;
    }
    __syncthreads();
}

__global__ void __launch_bounds__(NT, 1) lstm_kernel(
    const float* __restrict__ x,
    const float* __restrict__ Wi, const float* __restrict__ Wf,
    const float* __restrict__ Wo, const float* __restrict__ Wc,
    const float* __restrict__ Ui, const float* __restrict__ Uf,
    const float* __restrict__ Uo, const float* __restrict__ Uc,
    const float* __restrict__ bi, const float* __restrict__ bf,
    const float* __restrict__ bo, const float* __restrict__ bc,
    float* __restrict__ out)
{
    __shared__ float s_c[JPB][B_];  // persistent cell state for this block's columns
    __shared__ __align__(16) union SMu {
        struct { float xT[32][68]; float Ws[32][32]; } a;                       // phase A
        struct { float hT[128][B_]; float pre[4][JPB][B_]; float hsw[JPB][B_]; } b; // phase B
    } sm;

    const int tid = threadIdx.x;
    const int bid = blockIdx.x;
    unsigned phase = *(volatile unsigned*)&g_bar_release;  // race-free: no release can
                                                           // complete before every block arrives once

    // ---- zero h0 and the c0 output region; zero cell state ----
    {
        float* c0out = out + (size_t)S_ * B_ * H_ + (size_t)B_ * H_;
        for (int i = bid * NT + tid; i < H_ * B_; i += GRID * NT) {
            g_h[0][i] = 0.0f;
            c0out[i]  = 0.0f;
        }
    }
    s_c[tid >> 6][tid & 63] = 0.0f;

    const float* Wg[4]  = {Wi, Wf, Wo, Wc};
    const float* Ug4[4] = {Ui, Uf, Uo, Uc};
    const float* bg[4]  = {bi, bf, bo, bc};

    // ================= Phase A: gx[s][g][j][b] = x[s] @ W_g + b_g =================
    {
        const int tx = tid & 15;   // b-group: b0 = tx*4
        const int ty = tid >> 4;   // j-group: j  = j0 + ty*2 + {0,1}
        for (int item = bid; item < S_ * 64; item += GRID) {
            const int s  = item >> 6;
            const int g  = (item >> 4) & 3;
            const int j0 = (item & 15) * 32;
            const float* W  = Wg[g];
            const float* xs = x + (size_t)s * B_ * I_;

            float a00 = 0, a01 = 0, a02 = 0, a03 = 0;
            float a10 = 0, a11 = 0, a12 = 0, a13 = 0;

            // register-pipelined prefetch of first k-chunk
            float4 xr0, xr1, wr;
            {
                int fi = tid, row = fi >> 3, c4 = fi & 7;
                xr0 = *(const float4*)(xs + row * I_ + c4 * 4);
                fi = tid + 256; row = fi >> 3; c4 = fi & 7;
                xr1 = *(const float4*)(xs + row * I_ + c4 * 4);
                int wrow = tid >> 3, wc4 = tid & 7;
                wr = *(const float4*)(W + wrow * H_ + j0 + wc4 * 4);
            }
            for (int kc = 0; kc < I_; kc += 32) {
                __syncthreads();
                {   // store prefetched tiles (x transposed so b is contiguous)
                    int fi = tid, row = fi >> 3, c4 = fi & 7;
                    sm.a.xT[c4 * 4 + 0][row] = xr0.x; sm.a.xT[c4 * 4 + 1][row] = xr0.y;
                    sm.a.xT[c4 * 4 + 2][row] = xr0.z; sm.a.xT[c4 * 4 + 3][row] = xr0.w;
                    fi = tid + 256; row = fi >> 3; c4 = fi & 7;
                    sm.a.xT[c4 * 4 + 0][row] = xr1.x; sm.a.xT[c4 * 4 + 1][row] = xr1.y;
                    sm.a.xT[c4 * 4 + 2][row] = xr1.z; sm.a.xT[c4 * 4 + 3][row] = xr1.w;
                    int wrow = tid >> 3, wc4 = tid & 7;
                    *(float4*)&sm.a.Ws[wrow][wc4 * 4] = wr;
                }
                __syncthreads();
                if (kc + 32 < I_) {   // prefetch next chunk (latency hidden under compute)
                    int kn = kc + 32;
                    int fi = tid, row = fi >> 3, c4 = fi & 7;
                    xr0 = *(const float4*)(xs + row * I_ + kn + c4 * 4);
                    fi = tid + 256; row = fi >> 3; c4 = fi & 7;
                    xr1 = *(const float4*)(xs + row * I_ + kn + c4 * 4);
                    int wrow = tid >> 3, wc4 = tid & 7;
                    wr = *(const float4*)(W + (kn + wrow) * H_ + j0 + wc4 * 4);
                }
                #pragma unroll
                for (int k = 0; k < 32; k++) {
                    float4 xv = *(const float4*)&sm.a.xT[k][tx * 4];
                    float2 wv = *(const float2*)&sm.a.Ws[k][ty * 2];
                    a00 += xv.x * wv.x; a01 += xv.y * wv.x; a02 += xv.z * wv.x; a03 += xv.w * wv.x;
                    a10 += xv.x * wv.y; a11 += xv.y * wv.y; a12 += xv.z * wv.y; a13 += xv.w * wv.y;
                }
            }
            float bj0 = bg[g][j0 + ty * 2 + 0];
            float bj1 = bg[g][j0 + ty * 2 + 1];
            float* dst = g_gx + (((size_t)s * 4 + g) * H_ + j0 + ty * 2) * B_ + tx * 4;
            *(float4*)dst        = make_float4(a00 + bj0, a01 + bj0, a02 + bj0, a03 + bj0);
            *(float4*)(dst + B_) = make_float4(a10 + bj1, a11 + bj1, a12 + bj1, a13 + bj1);
        }
        __syncthreads();
    }

    grid_barrier(phase);

    // ================= Phase B: 512 sequential recurrence steps =================
    // Worker block w owns hidden columns j0..j0+3 for ALL 4 gates -> activations local.
    const bool worker = (bid < NWORK);
    const int  w    = tid >> 5;
    const int  lane = tid & 31;
    const int  g    = w >> 1;                 // warp's gate (0..3)
    const int  b    = (w & 1) * 32 + lane;    // warp-pair covers all 64 batch rows
    const int  j0   = bid * JPB;
    const float* U  = Ug4[g];

    for (int s = 0; s < S_; s++) {
        if (worker) {
            const float* hcur = g_h[s & 1];
            float acc0, acc1, acc2, acc3;
            {
                const float* gxp = g_gx + (((size_t)s * 4 + g) * H_ + j0) * B_ + b;
                acc0 = gxp[0];       acc1 = gxp[B_];
                acc2 = gxp[2 * B_];  acc3 = gxp[3 * B_];
            }
            // register-pipelined h tile (shared-K operand); [j][b] layout -> straight copy
            float4 hr[8];
            #pragma unroll
            for (int r = 0; r < 8; r++) hr[r] = ((const float4*)hcur)[tid + r * 256];

            for (int kc = 0; kc < H_; kc += 128) {
                __syncthreads();
                #pragma unroll
                for (int r = 0; r < 8; r++) ((float4*)sm.b.hT)[tid + r * 256] = hr[r];
                __syncthreads();
                if (kc + 128 < H_) {
                    const float4* src = (const float4*)(hcur + (kc + 128) * B_);
                    #pragma unroll
                    for (int r = 0; r < 8; r++) hr[r] = src[tid + r * 256];
                }
                const float* Ub = U + (size_t)kc * H_ + j0;
                #pragma unroll 16
                for (int k = 0; k < 128; k++) {
                    float  hv = sm.b.hT[k][b];                       // conflict-free LDS
                    float4 u  = *(const float4*)(Ub + (size_t)k * H_); // uniform LDG.128, L1-hit
                    acc0 += hv * u.x; acc1 += hv * u.y; acc2 += hv * u.z; acc3 += hv * u.w;
                }
            }
            // gate exchange + activations (all local to the block)
            sm.b.pre[g][0][b] = acc0;
            sm.b.pre[g][1][b] = acc1;
            sm.b.pre[g][2][b] = acc2;
            sm.b.pre[g][3][b] = acc3;
            __syncthreads();
            {
                const int jj = tid >> 6, b2 = tid & 63;
                float gi = sm.b.pre[0][jj][b2];
                float gf = sm.b.pre[1][jj][b2];
                float go = sm.b.pre[2][jj][b2];
                float gc = sm.b.pre[3][jj][b2];
                float it = 1.0f / (1.0f + __expf(-gi));
                float ft = 1.0f / (1.0f + __expf(-gf));
                float ot = 1.0f / (1.0f + __expf(-go));
                float ct = tanhf(gc);
                float cn = ft * s_c[jj][b2] + it * ct;
                s_c[jj][b2] = cn;
                float hn = ot * tanhf(cn);
                g_h[(s + 1) & 1][(j0 + jj) * B_ + b2] = hn;  // coalesced [j][b] store
                sm.b.hsw[jj][b2] = hn;
            }
            __syncthreads();
            if (tid < B_) {  // transposed in smem -> vectorized hs[s][b][j] store
                float4 hv = make_float4(sm.b.hsw[0][tid], sm.b.hsw[1][tid],
                                        sm.b.hsw[2][tid], sm.b.hsw[3][tid]);
                *(float4*)(out + ((size_t)s * B_ + tid) * H_ + j0) = hv;
                if (s == S_ - 1)
                    *(float4*)(out + (size_t)S_ * B_ * H_ + (size_t)tid * H_ + j0) = hv;
            }
        }
        grid_barrier(phase);
    }
}

extern "C" void kernel_launch(void* const* d_in, const int* in_sizes, int n_in,
                              void* d_out, int out_size) {
    (void)in_sizes; (void)n_in; (void)out_size;
    lstm_kernel<<<GRID, NT>>>(
        (const float*)d_in[0],
        (const float*)d_in[1], (const float*)d_in[2], (const float*)d_in[3], (const float*)d_in[4],
        (const float*)d_in[5], (const float*)d_in[6], (const float*)d_in[7], (const float*)d_in[8],
        (const float*)d_in[9], (const float*)d_in[10], (const float*)d_in[11], (const float*)d_in[12],
        (float*)d_out);
}

// round 2
// speedup vs baseline: 1.5502x; 1.5502x over previous
#include <cuda_runtime.h>

#define S_    512
#define B_    64
#define I_    512
#define H_    512
#define GRID  148
#define NT    256
#define NWORK 128
#define JPB   4

// Dynamic smem layout:
//  phase A: xT[32][68] (8704B) + Ws[32][32] (4096B)
//  phase B: Usm float4[4*512] (32768B) + red float[4096] (16384B) + hsw[256] (1024B)
#define SMEM_DYN (32768 + 16384 + 1024)

// Scratch (device globals: allocation-free rule)
__device__ float    g_gx[(size_t)S_ * 4 * H_ * B_];   // [s][gate][j][b]
__device__ float    g_h[2][H_ * B_];                  // [buf][j][b] double-buffered hidden
__device__ unsigned g_bar_count;
__device__ unsigned g_bar_release;

// Grid-wide barrier (grid == SM count, 1 block/SM -> all resident).
// __threadfence() (gpu scope) emits CCTL.IVALL: L1D flushed, so cross-SM h
// updates are never stale. U lives in SMEM so the flush doesn't evict it.
__device__ __forceinline__ void grid_barrier(unsigned& phase) {
    __syncthreads();
    if (threadIdx.x == 0) {
        __threadfence();
        unsigned ticket = atomicAdd(&g_bar_count, 1u);
        if (ticket == (unsigned)(gridDim.x - 1)) {
            g_bar_count = 0u;
            __threadfence();
            atomicAdd(&g_bar_release, 1u);
        } else {
            volatile unsigned* rel = &g_bar_release;
            while (*rel == phase) { }
        }
        __threadfence();
        phase += 1u;
    }
    __syncthreads();
}

__global__ void __launch_bounds__(NT, 1) lstm_kernel(
    const float* __restrict__ x,
    const float* __restrict__ Wi, const float* __restrict__ Wf,
    const float* __restrict__ Wo, const float* __restrict__ Wc,
    const float* __restrict__ Ui, const float* __restrict__ Uf,
    const float* __restrict__ Uo, const float* __restrict__ Uc,
    const float* __restrict__ bi, const float* __restrict__ bf,
    const float* __restrict__ bo, const float* __restrict__ bc,
    float* __restrict__ out)
{
    extern __shared__ __align__(16) char dynsm[];
    __shared__ float s_c[JPB][B_];   // persistent cell state for this block's columns

    const int tid = threadIdx.x;
    const int bid = blockIdx.x;
    unsigned phase = *(volatile unsigned*)&g_bar_release;

    // ---- zero h0 and the c0 output region; zero cell state ----
    {
        float* c0out = out + (size_t)S_ * B_ * H_ + (size_t)B_ * H_;
        for (int i = bid * NT + tid; i < H_ * B_; i += GRID * NT) {
            g_h[0][i] = 0.0f;
            c0out[i]  = 0.0f;
        }
    }
    s_c[tid >> 6][tid & 63] = 0.0f;

    const float* Wg[4]  = {Wi, Wf, Wo, Wc};
    const float* Ug4[4] = {Ui, Uf, Uo, Uc};
    const float* bg[4]  = {bi, bf, bo, bc};

    // ================= Phase A: gx[s][g][j][b] = x[s] @ W_g + b_g =================
    {
        float (*xT)[68] = reinterpret_cast<float(*)[68]>(dynsm);
        float (*Ws)[32] = reinterpret_cast<float(*)[32]>(dynsm + 32 * 68 * 4);
        const int tx = tid & 15;   // b-group: b0 = tx*4
        const int ty = tid >> 4;   // j-group: j  = j0 + ty*2 + {0,1}
        for (int item = bid; item < S_ * 64; item += GRID) {
            const int s  = item >> 6;
            const int g  = (item >> 4) & 3;
            const int j0 = (item & 15) * 32;
            const float* W  = Wg[g];
            const float* xs = x + (size_t)s * B_ * I_;

            float a00 = 0, a01 = 0, a02 = 0, a03 = 0;
            float a10 = 0, a11 = 0, a12 = 0, a13 = 0;

            float4 xr0, xr1, wr;
            {
                int fi = tid, row = fi >> 3, c4 = fi & 7;
                xr0 = *(const float4*)(xs + row * I_ + c4 * 4);
                fi = tid + 256; row = fi >> 3; c4 = fi & 7;
                xr1 = *(const float4*)(xs + row * I_ + c4 * 4);
                int wrow = tid >> 3, wc4 = tid & 7;
                wr = *(const float4*)(W + wrow * H_ + j0 + wc4 * 4);
            }
            for (int kc = 0; kc < I_; kc += 32) {
                __syncthreads();
                {
                    int fi = tid, row = fi >> 3, c4 = fi & 7;
                    xT[c4 * 4 + 0][row] = xr0.x; xT[c4 * 4 + 1][row] = xr0.y;
                    xT[c4 * 4 + 2][row] = xr0.z; xT[c4 * 4 + 3][row] = xr0.w;
                    fi = tid + 256; row = fi >> 3; c4 = fi & 7;
                    xT[c4 * 4 + 0][row] = xr1.x; xT[c4 * 4 + 1][row] = xr1.y;
                    xT[c4 * 4 + 2][row] = xr1.z; xT[c4 * 4 + 3][row] = xr1.w;
                    int wrow = tid >> 3, wc4 = tid & 7;
                    *(float4*)&Ws[wrow][wc4 * 4] = wr;
                }
                __syncthreads();
                if (kc + 32 < I_) {
                    int kn = kc + 32;
                    int fi = tid, row = fi >> 3, c4 = fi & 7;
                    xr0 = *(const float4*)(xs + row * I_ + kn + c4 * 4);
                    fi = tid + 256; row = fi >> 3; c4 = fi & 7;
                    xr1 = *(const float4*)(xs + row * I_ + kn + c4 * 4);
                    int wrow = tid >> 3, wc4 = tid & 7;
                    wr = *(const float4*)(W + (kn + wrow) * H_ + j0 + wc4 * 4);
                }
                #pragma unroll
                for (int k = 0; k < 32; k++) {
                    float4 xv = *(const float4*)&xT[k][tx * 4];
                    float2 wv = *(const float2*)&Ws[k][ty * 2];
                    a00 += xv.x * wv.x; a01 += xv.y * wv.x; a02 += xv.z * wv.x; a03 += xv.w * wv.x;
                    a10 += xv.x * wv.y; a11 += xv.y * wv.y; a12 += xv.z * wv.y; a13 += xv.w * wv.y;
                }
            }
            float bj0 = bg[g][j0 + ty * 2 + 0];
            float bj1 = bg[g][j0 + ty * 2 + 1];
            float* dst = g_gx + (((size_t)s * 4 + g) * H_ + j0 + ty * 2) * B_ + tx * 4;
            *(float4*)dst        = make_float4(a00 + bj0, a01 + bj0, a02 + bj0, a03 + bj0);
            *(float4*)(dst + B_) = make_float4(a10 + bj1, a11 + bj1, a12 + bj1, a13 + bj1);
        }
        __syncthreads();
    }

    // ================= Phase B setup: stage this block's U slice in SMEM =========
    float4* Usm = (float4*)dynsm;                               // [4][512] float4 (32KB)
    float*  red = (float*)(dynsm + 32768);                      // [4ks][4g][4j][64b] (16KB)
    float*  hsw = (float*)(dynsm + 32768 + 16384);              // [4j][64b] (1KB)

    const bool worker = (bid < NWORK);
    const int  j0 = bid * JPB;
    if (worker) {
        for (int idx = tid; idx < 4 * 512; idx += NT) {
            int gg = idx >> 9, kk = idx & 511;
            Usm[gg * 512 + kk] = *(const float4*)(Ug4[gg] + (size_t)kk * H_ + j0);
        }
    }
    __syncthreads();
    grid_barrier(phase);

    // ================= Phase B: 512 sequential recurrence steps ==================
    // 256 threads = 4 kslice x 4 gate x 16 b-quad; each thread: 4j x 4b outer
    // product over 128 k -> 16 FFMA per (1 LDG.128 + 1 LDS.128).
    const int ks = tid >> 6;
    const int g  = (tid >> 4) & 3;
    const int bq = tid & 15;
    const int jj = tid >> 6;     // epilogue role
    const int b2 = tid & 63;

    for (int s = 0; s < S_; s++) {
        if (worker) {
            const float* hcur = g_h[s & 1];
            float4 acc0 = {0,0,0,0}, acc1 = {0,0,0,0}, acc2 = {0,0,0,0}, acc3 = {0,0,0,0};
            const float4* hp = (const float4*)hcur + ks * 128 * 16 + bq;  // h[k][b0..b0+3]
            const float4* up = Usm + g * 512 + ks * 128;                  // U[k][j0..j0+3]
            #pragma unroll 8
            for (int k = 0; k < 128; k++) {
                float4 h4 = hp[(size_t)k * 16];
                float4 u  = up[k];
                acc0.x += u.x * h4.x; acc0.y += u.x * h4.y; acc0.z += u.x * h4.z; acc0.w += u.x * h4.w;
                acc1.x += u.y * h4.x; acc1.y += u.y * h4.y; acc1.z += u.y * h4.z; acc1.w += u.y * h4.w;
                acc2.x += u.z * h4.x; acc2.y += u.z * h4.y; acc2.z += u.z * h4.z; acc2.w += u.z * h4.w;
                acc3.x += u.w * h4.x; acc3.y += u.w * h4.y; acc3.z += u.w * h4.z; acc3.w += u.w * h4.w;
            }
            float4* redq = (float4*)red;
            int base = ((ks * 4 + g) * 4) * 16 + bq;
            redq[base]      = acc0;
            redq[base + 16] = acc1;
            redq[base + 32] = acc2;
            redq[base + 48] = acc3;
        }
        __syncthreads();
        if (worker) {
            // epilogue thread (jj, b2): reduce 4 kslices, add gx, activations
            float pre[4];
            #pragma unroll
            for (int gg = 0; gg < 4; gg++) {
                float v = red[((0 * 4 + gg) * 4 + jj) * 64 + b2]
                        + red[((1 * 4 + gg) * 4 + jj) * 64 + b2]
                        + red[((2 * 4 + gg) * 4 + jj) * 64 + b2]
                        + red[((3 * 4 + gg) * 4 + jj) * 64 + b2];
                v += g_gx[(((size_t)s * 4 + gg) * H_ + j0 + jj) * B_ + b2];
                pre[gg] = v;
            }
            float it = 1.0f / (1.0f + __expf(-pre[0]));
            float ft = 1.0f / (1.0f + __expf(-pre[1]));
            float ot = 1.0f / (1.0f + __expf(-pre[2]));
            float ct = tanhf(pre[3]);
            float cn = ft * s_c[jj][b2] + it * ct;
            s_c[jj][b2] = cn;
            float hn = ot * tanhf(cn);
            g_h[(s + 1) & 1][(j0 + jj) * B_ + b2] = hn;   // coalesced [j][b] store
            hsw[jj * 64 + b2] = hn;
        }
        __syncthreads();
        if (worker && tid < B_) {   // transposed smem -> vectorized hs[s][b][j] store
            float4 hv = make_float4(hsw[tid], hsw[64 + tid], hsw[128 + tid], hsw[192 + tid]);
            *(float4*)(out + ((size_t)s * B_ + tid) * H_ + j0) = hv;
            if (s == S_ - 1)
                *(float4*)(out + (size_t)S_ * B_ * H_ + (size_t)tid * H_ + j0) = hv;
        }
        grid_barrier(phase);
    }
}

extern "C" void kernel_launch(void* const* d_in, const int* in_sizes, int n_in,
                              void* d_out, int out_size) {
    (void)in_sizes; (void)n_in; (void)out_size;
    cudaFuncSetAttribute(lstm_kernel, cudaFuncAttributeMaxDynamicSharedMemorySize, SMEM_DYN);
    lstm_kernel<<<GRID, NT, SMEM_DYN>>>(
        (const float*)d_in[0],
        (const float*)d_in[1], (const float*)d_in[2], (const float*)d_in[3], (const float*)d_in[4],
        (const float*)d_in[5], (const float*)d_in[6], (const float*)d_in[7], (const float*)d_in[8],
        (const float*)d_in[9], (const float*)d_in[10], (const float*)d_in[11], (const float*)d_in[12],
        (float*)d_out);
}

// round 3
// speedup vs baseline: 1.8784x; 1.2117x over previous
#include <cuda_runtime.h>

#define S_    512
#define B_    64
#define I_    512
#define H_    512
#define GRID  148
#define NT    512
#define NWORK 128
#define JPB   4

// Dynamic smem:
//  phase A: xT[32][68] (8704B) + Ws[32][64] (8192B)            = 16896B
//  phase B: Usm float4[4*512] (32KB) + red[8192] (32KB) + hsw (1KB) = 66560B
#define SMEM_DYN 66560

__device__ float    g_gx[(size_t)S_ * 4 * H_ * B_];   // [s][gate][j][b]
__device__ float    g_h[2][H_ * B_];                  // [buf][j][b]
__device__ unsigned g_bar_count;
__device__ unsigned g_bar_release;

// Grid barrier. __threadfence() (gpu scope) emits CCTL.IVALL -> L1 flushed,
// so cross-SM h updates are never stale. U lives in SMEM, unaffected.
__device__ __forceinline__ void grid_barrier(unsigned& phase, unsigned expected) {
    __syncthreads();
    if (threadIdx.x == 0) {
        __threadfence();
        unsigned ticket = atomicAdd(&g_bar_count, 1u);
        if (ticket == expected - 1u) {
            g_bar_count = 0u;
            __threadfence();
            atomicAdd(&g_bar_release, 1u);
        } else {
            volatile unsigned* rel = &g_bar_release;
            while (*rel == phase) { }
        }
        __threadfence();
        phase += 1u;
    }
    __syncthreads();
}

__global__ void __launch_bounds__(NT, 1) lstm_kernel(
    const float* __restrict__ x,
    const float* __restrict__ Wi, const float* __restrict__ Wf,
    const float* __restrict__ Wo, const float* __restrict__ Wc,
    const float* __restrict__ Ui, const float* __restrict__ Uf,
    const float* __restrict__ Uo, const float* __restrict__ Uc,
    const float* __restrict__ bi, const float* __restrict__ bf,
    const float* __restrict__ bo, const float* __restrict__ bc,
    float* __restrict__ out)
{
    extern __shared__ __align__(16) char dynsm[];
    __shared__ float s_c[JPB][B_];

    const int tid = threadIdx.x;
    const int bid = blockIdx.x;
    unsigned phase = *(volatile unsigned*)&g_bar_release;  // safe: no release can
                                                           // complete before every block arrives once

    // ---- zero h0 + c0 output region + cell state ----
    {
        float* c0out = out + (size_t)S_ * B_ * H_ + (size_t)B_ * H_;
        for (int i = bid * NT + tid; i < H_ * B_; i += GRID * NT) {
            g_h[0][i] = 0.0f;
            c0out[i]  = 0.0f;
        }
    }
    if (tid < 256) s_c[tid >> 6][tid & 63] = 0.0f;

    const float* Wg[4]  = {Wi, Wf, Wo, Wc};
    const float* Ug4[4] = {Ui, Uf, Uo, Uc};
    const float* bg[4]  = {bi, bf, bo, bc};

    // ================= Phase A: gx[s][g][j][b] = x[s] @ W_g + b_g =================
    // item = (s, gate, 64-wide j block); 512 threads; per-thread 4b x 2j tile.
    {
        float (*xT)[68] = reinterpret_cast<float(*)[68]>(dynsm);
        float (*Ws)[64] = reinterpret_cast<float(*)[64]>(dynsm + 32 * 68 * 4);
        const int tx = tid & 15;    // b-quad
        const int ty = tid >> 4;    // 0..31 -> j = j0 + ty*2 + {0,1}
        const int xrow = tid >> 3, xc4 = tid & 7;     // x loader role
        const int wrow = tid >> 4, wc4 = tid & 15;    // W loader role

        for (int item = bid; item < S_ * 32; item += GRID) {
            const int s  = item >> 5;
            const int g  = (item >> 3) & 3;
            const int j0 = (item & 7) * 64;
            const float* W  = Wg[g];
            const float* xs = x + (size_t)s * B_ * I_;

            float a00 = 0, a01 = 0, a02 = 0, a03 = 0;
            float a10 = 0, a11 = 0, a12 = 0, a13 = 0;

            float4 xr = *(const float4*)(xs + xrow * I_ + xc4 * 4);
            float4 wr = *(const float4*)(W + wrow * H_ + j0 + wc4 * 4);

            for (int kc = 0; kc < I_; kc += 32) {
                __syncthreads();
                xT[xc4 * 4 + 0][xrow] = xr.x; xT[xc4 * 4 + 1][xrow] = xr.y;
                xT[xc4 * 4 + 2][xrow] = xr.z; xT[xc4 * 4 + 3][xrow] = xr.w;
                *(float4*)&Ws[wrow][wc4 * 4] = wr;
                __syncthreads();
                if (kc + 32 < I_) {
                    xr = *(const float4*)(xs + xrow * I_ + (kc + 32) + xc4 * 4);
                    wr = *(const float4*)(W + (size_t)(kc + 32 + wrow) * H_ + j0 + wc4 * 4);
                }
                #pragma unroll
                for (int k = 0; k < 32; k++) {
                    float4 xv = *(const float4*)&xT[k][tx * 4];
                    float2 wv = *(const float2*)&Ws[k][ty * 2];
                    a00 += xv.x * wv.x; a01 += xv.y * wv.x; a02 += xv.z * wv.x; a03 += xv.w * wv.x;
                    a10 += xv.x * wv.y; a11 += xv.y * wv.y; a12 += xv.z * wv.y; a13 += xv.w * wv.y;
                }
            }
            float bj0 = bg[g][j0 + ty * 2 + 0];
            float bj1 = bg[g][j0 + ty * 2 + 1];
            float* dst = g_gx + (((size_t)s * 4 + g) * H_ + j0 + ty * 2) * B_ + tx * 4;
            *(float4*)dst        = make_float4(a00 + bj0, a01 + bj0, a02 + bj0, a03 + bj0);
            *(float4*)(dst + B_) = make_float4(a10 + bj1, a11 + bj1, a12 + bj1, a13 + bj1);
        }
        __syncthreads();
    }

    // ================= Phase B setup: stage U slice in SMEM =======================
    float4* Usm = (float4*)dynsm;                          // [4g][512k] float4 (32KB)
    float*  red = (float*)(dynsm + 32768);                 // [8ks][4g][4j][64b] (32KB)
    float*  hsw = (float*)(dynsm + 32768 + 32768);         // [4j][64b] (1KB)

    const bool worker = (bid < NWORK);
    const int  j0 = bid * JPB;
    if (worker) {
        for (int idx = tid; idx < 4 * 512; idx += NT) {
            int gg = idx >> 9, kk = idx & 511;
            Usm[gg * 512 + kk] = *(const float4*)(Ug4[gg] + (size_t)kk * H_ + j0);
        }
    }
    __syncthreads();
    grid_barrier(phase, GRID);
    if (!worker) return;

    // ================= Phase B: 512 sequential recurrence steps ===================
    // 512 threads = 8 kslice x 4 gate x 16 b-quad; per thread 4j x 4b over K=64:
    // 16 FFMA per (1 LDG.128 [L1-dedup across gates] + 1 LDS.128).
    const int ks = tid >> 6;          // 0..7
    const int g  = (tid >> 4) & 3;
    const int bq = tid & 15;
    const int jj = tid >> 6;          // epilogue role (tid < 256)
    const int b2 = tid & 63;

    for (int s = 0; s < S_; s++) {
        // prefetch gx for epilogue (completes under the FMA loop)
        float gx0, gx1, gx2, gx3;
        if (tid < 256) {
            const float* gxp = g_gx + (((size_t)s * 4) * H_ + j0 + jj) * B_ + b2;
            gx0 = gxp[0];
            gx1 = gxp[(size_t)H_ * B_];
            gx2 = gxp[(size_t)2 * H_ * B_];
            gx3 = gxp[(size_t)3 * H_ * B_];
        }
        {
            const float4* hp = (const float4*)g_h[s & 1] + (ks << 10) + bq;  // + k*16
            const float4* up = Usm + (g << 9) + (ks << 6);
            float4 a0 = {0,0,0,0}, a1 = {0,0,0,0}, a2 = {0,0,0,0}, a3 = {0,0,0,0};
            #pragma unroll 8
            for (int k = 0; k < 64; k++) {
                float4 h4 = hp[k << 4];
                float4 u  = up[k];
                a0.x += u.x * h4.x; a0.y += u.x * h4.y; a0.z += u.x * h4.z; a0.w += u.x * h4.w;
                a1.x += u.y * h4.x; a1.y += u.y * h4.y; a1.z += u.y * h4.z; a1.w += u.y * h4.w;
                a2.x += u.z * h4.x; a2.y += u.z * h4.y; a2.z += u.z * h4.z; a2.w += u.z * h4.w;
                a3.x += u.w * h4.x; a3.y += u.w * h4.y; a3.z += u.w * h4.z; a3.w += u.w * h4.w;
            }
            float4* redq = (float4*)red;
            int base = ((ks * 4 + g) * 4) * 16 + bq;
            redq[base]      = a0;
            redq[base + 16] = a1;
            redq[base + 32] = a2;
            redq[base + 48] = a3;
        }
        __syncthreads();
        if (tid < 256) {
            float pre[4] = {gx0, gx1, gx2, gx3};
            #pragma unroll
            for (int gg = 0; gg < 4; gg++) {
                float v = pre[gg];
                #pragma unroll
                for (int k8 = 0; k8 < 8; k8++)
                    v += red[((k8 * 4 + gg) * 4 + jj) * 64 + b2];
                pre[gg] = v;
            }
            float it = 1.0f / (1.0f + __expf(-pre[0]));
            float ft = 1.0f / (1.0f + __expf(-pre[1]));
            float ot = 1.0f / (1.0f + __expf(-pre[2]));
            float ct = tanhf(pre[3]);
            float cn = ft * s_c[jj][b2] + it * ct;
            s_c[jj][b2] = cn;
            float hn = ot * tanhf(cn);
            g_h[(s + 1) & 1][(j0 + jj) * B_ + b2] = hn;
            hsw[jj * 64 + b2] = hn;
        }
        __syncthreads();
        if (tid < B_) {
            float4 hv = make_float4(hsw[tid], hsw[64 + tid], hsw[128 + tid], hsw[192 + tid]);
            *(float4*)(out + ((size_t)s * B_ + tid) * H_ + j0) = hv;
            if (s == S_ - 1)
                *(float4*)(out + (size_t)S_ * B_ * H_ + (size_t)tid * H_ + j0) = hv;
        }
        if (s < S_ - 1) grid_barrier(phase, NWORK);
    }
}

extern "C" void kernel_launch(void* const* d_in, const int* in_sizes, int n_in,
                              void* d_out, int out_size) {
    (void)in_sizes; (void)n_in; (void)out_size;
    cudaFuncSetAttribute(lstm_kernel, cudaFuncAttributeMaxDynamicSharedMemorySize, SMEM_DYN);
    lstm_kernel<<<GRID, NT, SMEM_DYN>>>(
        (const float*)d_in[0],
        (const float*)d_in[1], (const float*)d_in[2], (const float*)d_in[3], (const float*)d_in[4],
        (const float*)d_in[5], (const float*)d_in[6], (const float*)d_in[7], (const float*)d_in[8],
        (const float*)d_in[9], (const float*)d_in[10], (const float*)d_in[11], (const float*)d_in[12],
        (float*)d_out);
}

// round 6
// speedup vs baseline: 2.6465x; 1.4090x over previous
#include <cuda_runtime.h>
#include <cuda_bf16.h>
#include <cstdint>

#define S_    512
#define B_    64
#define I_    512
#define H_    512
#define SB_   (S_ * B_)
#define JG_   (4 * H_)
#define NWORK 128
#define NTB   512
#define JPB   4

// ---------------- device globals (no allocs allowed) ----------------
__device__ float         g_gx[(size_t)S_ * 4 * H_ * B_];   // [s][gate][j][b]
__device__ float         g_h[2][H_ * B_];                  // [buf][j][b]
__device__ __nv_bfloat16 g_xhi[(size_t)SB_ * I_];
__device__ __nv_bfloat16 g_xlo[(size_t)SB_ * I_];
__device__ __nv_bfloat16 g_wthi[(size_t)JG_ * I_];         // Wt[jg][k] = W_g[k][j]
__device__ __nv_bfloat16 g_wtlo[(size_t)JG_ * I_];
__device__ unsigned      g_bar_count;
__device__ unsigned      g_bar_release;

// ---------------- helpers ----------------
__device__ __forceinline__ uint32_t smem_u32(const void* p) {
    uint32_t a;
    asm("{ .reg .u64 t; cvta.to.shared.u64 t, %1; cvt.u32.u64 %0, t; }" : "=r"(a) : "l"(p));
    return a;
}
__device__ __forceinline__ void cp16(uint32_t dst, const void* src) {
    asm volatile("cp.async.ca.shared.global [%0], [%1], 16;" :: "r"(dst), "l"(src));
}
#define CP_COMMIT() asm volatile("cp.async.commit_group;" ::: "memory")
#define CP_WAIT1()  asm volatile("cp.async.wait_group 1;" ::: "memory")
#define CP_WAIT0()  asm volatile("cp.async.wait_group 0;" ::: "memory")

__device__ __forceinline__ void mma16816(float* d, const uint32_t* a, const uint32_t* b) {
    asm volatile(
        "mma.sync.aligned.m16n8k16.row.col.f32.bf16.bf16.f32 "
        "{%0,%1,%2,%3}, {%4,%5,%6,%7}, {%8,%9}, {%0,%1,%2,%3};"
        : "+f"(d[0]), "+f"(d[1]), "+f"(d[2]), "+f"(d[3])
        : "r"(a[0]), "r"(a[1]), "r"(a[2]), "r"(a[3]), "r"(b[0]), "r"(b[1]));
}

// =====================================================================
// Kernel 1: prep — bf16 hi/lo of x, W^T hi/lo, zero h0 + c0 output
// =====================================================================
__global__ void prep_kernel(const float* __restrict__ x,
                            const float* __restrict__ Wi, const float* __restrict__ Wf,
                            const float* __restrict__ Wo, const float* __restrict__ Wc,
                            float* __restrict__ out)
{
    const int stride = gridDim.x * blockDim.x;
    const int t0 = blockIdx.x * blockDim.x + threadIdx.x;
    for (size_t i = t0; i < (size_t)SB_ * I_; i += stride) {
        float v = x[i];
        __nv_bfloat16 hi = __float2bfloat16_rn(v);
        g_xhi[i] = hi;
        g_xlo[i] = __float2bfloat16_rn(v - __bfloat162float(hi));
    }
    const float* Wg[4] = {Wi, Wf, Wo, Wc};
    for (size_t i = t0; i < (size_t)JG_ * I_; i += stride) {
        int jg = (int)(i >> 9), k = (int)(i & 511);
        int g = jg >> 9, j = jg & 511;
        float v = Wg[g][(size_t)k * H_ + j];
        __nv_bfloat16 hi = __float2bfloat16_rn(v);
        g_wthi[i] = hi;
        g_wtlo[i] = __float2bfloat16_rn(v - __bfloat162float(hi));
    }
    float* c0out = out + (size_t)S_ * B_ * H_ + (size_t)B_ * H_;
    for (int i = t0; i < H_ * B_; i += stride) {
        g_h[0][i] = 0.0f;
        c0out[i]  = 0.0f;
    }
}

// =====================================================================
// Kernel 2: mma.sync bf16 3-split GEMM, gx = x @ W + b
// tile: M=128(sb) x N=64(jg), K=512 in 16 chunks of 32, cp.async 2-buf
// =====================================================================
#define PADK    40
#define AS_ELE  (128 * PADK)
#define BS_ELE  (64 * PADK)
#define SM_BS   (4 * AS_ELE * 2)               // 40960
#define SM_BIAS (SM_BS + 4 * BS_ELE * 2)       // 61440
#define SM_TOT  (SM_BIAS + 256)                // 61696

__global__ void __launch_bounds__(256, 2) gemm_a_kernel(
    const float* __restrict__ bi, const float* __restrict__ bf,
    const float* __restrict__ bo, const float* __restrict__ bc)
{
    extern __shared__ __align__(16) char sm[];
    const uint32_t smb = smem_u32(sm);
    __nv_bfloat16* As = (__nv_bfloat16*)sm;                 // [2buf][2sp][128][40]
    __nv_bfloat16* Bs = (__nv_bfloat16*)(sm + SM_BS);       // [2buf][2sp][64][40]
    float* bias_s = (float*)(sm + SM_BIAS);
    float* Ct = (float*)sm;                                 // alias after compute

    const int tid  = threadIdx.x;
    const int lane = tid & 31, wid = tid >> 5;
    const int wm = wid & 3, wn = wid >> 2;
    const int g5 = lane >> 2, tig = lane & 3;

    const int n0 = (blockIdx.x & 31) * 64;
    const int m0 = (blockIdx.x >> 5) * 128;
    const int gblk = n0 >> 9, j0 = n0 & 511;

    if (tid < 64) {
        const float* bg4[4] = {bi, bf, bo, bc};
        bias_s[tid] = bg4[gblk][j0 + tid];
    }

    float acc[2][4][4];
    #pragma unroll
    for (int mf = 0; mf < 2; mf++)
        #pragma unroll
        for (int nf = 0; nf < 4; nf++)
            #pragma unroll
            for (int q = 0; q < 4; q++) acc[mf][nf][q] = 0.0f;

    auto loadAB = [&](int buf, int kc) {
        #pragma unroll
        for (int i = 0; i < 4; i++) {           // A: 2sp x 128r x 4 chunks
            int idx = tid + i * 256;
            int sp = idx >> 9, rem = idx & 511, row = rem >> 2, kcol = rem & 3;
            const __nv_bfloat16* src =
                (sp ? g_xlo : g_xhi) + (size_t)(m0 + row) * I_ + kc + kcol * 8;
            uint32_t dst = smb + ((buf * 2 + sp) * AS_ELE + row * PADK + kcol * 8) * 2;
            cp16(dst, src);
        }
        #pragma unroll
        for (int i = 0; i < 2; i++) {           // B: 2sp x 64r x 4 chunks
            int idx = tid + i * 256;
            int sp = idx >> 8, rem = idx & 255, row = rem >> 2, kcol = rem & 3;
            const __nv_bfloat16* src =
                (sp ? g_wtlo : g_wthi) + (size_t)(n0 + row) * I_ + kc + kcol * 8;
            uint32_t dst = smb + SM_BS + ((buf * 2 + sp) * BS_ELE + row * PADK + kcol * 8) * 2;
            cp16(dst, src);
        }
    };

    loadAB(0, 0);  CP_COMMIT();
    loadAB(1, 32); CP_COMMIT();

    for (int kc = 0; kc < 16; kc++) {
        if (kc == 15) CP_WAIT0(); else CP_WAIT1();
        __syncthreads();
        const int buf = kc & 1;
        const __nv_bfloat16* Ah = As + (buf * 2 + 0) * AS_ELE;
        const __nv_bfloat16* Al = As + (buf * 2 + 1) * AS_ELE;
        const __nv_bfloat16* Bh = Bs + (buf * 2 + 0) * BS_ELE;
        const __nv_bfloat16* Bl = Bs + (buf * 2 + 1) * BS_ELE;
        #pragma unroll
        for (int k16 = 0; k16 < 2; k16++) {
            const int ko = k16 * 16 + 2 * tig;
            uint32_t ah[2][4], al[2][4], bh[4][2], bl[4][2];
            #pragma unroll
            for (int mf = 0; mf < 2; mf++) {
                int r0 = wm * 32 + mf * 16 + g5;
                ah[mf][0] = *(const uint32_t*)(Ah + r0 * PADK + ko);
                ah[mf][1] = *(const uint32_t*)(Ah + (r0 + 8) * PADK + ko);
                ah[mf][2] = *(const uint32_t*)(Ah + r0 * PADK + ko + 8);
                ah[mf][3] = *(const uint32_t*)(Ah + (r0 + 8) * PADK + ko + 8);
                al[mf][0] = *(const uint32_t*)(Al + r0 * PADK + ko);
                al[mf][1] = *(const uint32_t*)(Al + (r0 + 8) * PADK + ko);
                al[mf][2] = *(const uint32_t*)(Al + r0 * PADK + ko + 8);
                al[mf][3] = *(const uint32_t*)(Al + (r0 + 8) * PADK + ko + 8);
            }
            #pragma unroll
            for (int nf = 0; nf < 4; nf++) {
                int n = wn * 32 + nf * 8 + g5;
                bh[nf][0] = *(const uint32_t*)(Bh + n * PADK + ko);
                bh[nf][1] = *(const uint32_t*)(Bh + n * PADK + ko + 8);
                bl[nf][0] = *(const uint32_t*)(Bl + n * PADK + ko);
                bl[nf][1] = *(const uint32_t*)(Bl + n * PADK + ko + 8);
            }
            #pragma unroll
            for (int mf = 0; mf < 2; mf++)
                #pragma unroll
                for (int nf = 0; nf < 4; nf++) {
                    mma16816(acc[mf][nf], ah[mf], bh[nf]);
                    mma16816(acc[mf][nf], al[mf], bh[nf]);
                    mma16816(acc[mf][nf], ah[mf], bl[nf]);
                }
        }
        __syncthreads();
        if (kc < 14) { loadAB(buf, (kc + 2) * 32); CP_COMMIT(); }
    }

    // ---- epilogue: accums -> smem tile -> coalesced gx (+bias) ----
    #pragma unroll
    for (int mf = 0; mf < 2; mf++)
        #pragma unroll
        for (int nf = 0; nf < 4; nf++) {
            int r = wm * 32 + mf * 16 + g5;
            int c = wn * 32 + nf * 8 + 2 * tig;
            Ct[r * 65 + c]           = acc[mf][nf][0];
            Ct[r * 65 + c + 1]       = acc[mf][nf][1];
            Ct[(r + 8) * 65 + c]     = acc[mf][nf][2];
            Ct[(r + 8) * 65 + c + 1] = acc[mf][nf][3];
        }
    __syncthreads();
    {
        const int r = tid & 127, ch = tid >> 7;
        const int s = (m0 + r) >> 6, b = (m0 + r) & 63;
        float* dst = g_gx + (((size_t)s * 4 + gblk) * H_ + j0 + ch * 32) * B_ + b;
        #pragma unroll
        for (int c = 0; c < 32; c++)
            dst[(size_t)c * B_] = Ct[r * 65 + ch * 32 + c] + bias_s[ch * 32 + c];
    }
}

// =====================================================================
// Kernel 3: SIMT recurrence (proven R3 phase B)
// =====================================================================
#define SMEM_B_DYN (32768 + 32768 + 1024)

__device__ __forceinline__ void grid_barrier(unsigned& phase, unsigned expected) {
    __syncthreads();
    if (threadIdx.x == 0) {
        __threadfence();
        unsigned ticket = atomicAdd(&g_bar_count, 1u);
        if (ticket == expected - 1u) {
            g_bar_count = 0u;
            __threadfence();
            atomicAdd(&g_bar_release, 1u);
        } else {
            volatile unsigned* rel = &g_bar_release;
            while (*rel == phase) { }
        }
        __threadfence();
        phase += 1u;
    }
    __syncthreads();
}

__global__ void __launch_bounds__(NTB, 1) lstm_b_kernel(
    const float* __restrict__ Ui, const float* __restrict__ Uf,
    const float* __restrict__ Uo, const float* __restrict__ Uc,
    float* __restrict__ out)
{
    extern __shared__ __align__(16) char dynsm[];
    __shared__ float s_c[JPB][B_];

    const int tid = threadIdx.x;
    const int bid = blockIdx.x;
    unsigned phase = *(volatile unsigned*)&g_bar_release;

    if (tid < 256) s_c[tid >> 6][tid & 63] = 0.0f;

    float4* Usm = (float4*)dynsm;
    float*  red = (float*)(dynsm + 32768);
    float*  hsw = (float*)(dynsm + 32768 + 32768);

    const float* Ug4[4] = {Ui, Uf, Uo, Uc};
    const int j0 = bid * JPB;
    for (int idx = tid; idx < 4 * 512; idx += NTB) {
        int gg = idx >> 9, kk = idx & 511;
        Usm[gg * 512 + kk] = *(const float4*)(Ug4[gg] + (size_t)kk * H_ + j0);
    }
    __syncthreads();

    const int ks = tid >> 6;
    const int g  = (tid >> 4) & 3;
    const int bq = tid & 15;
    const int jj = tid >> 6;
    const int b2 = tid & 63;

    for (int s = 0; s < S_; s++) {
        float gx0, gx1, gx2, gx3;
        if (tid < 256) {
            const float* gxp = g_gx + (((size_t)s * 4) * H_ + j0 + jj) * B_ + b2;
            gx0 = gxp[0];
            gx1 = gxp[(size_t)H_ * B_];
            gx2 = gxp[(size_t)2 * H_ * B_];
            gx3 = gxp[(size_t)3 * H_ * B_];
        }
        {
            const float4* hp = (const float4*)g_h[s & 1] + (ks << 10) + bq;
            const float4* up = Usm + (g << 9) + (ks << 6);
            float4 a0 = {0,0,0,0}, a1 = {0,0,0,0}, a2 = {0,0,0,0}, a3 = {0,0,0,0};
            #pragma unroll 8
            for (int k = 0; k < 64; k++) {
                float4 h4 = hp[k << 4];
                float4 u  = up[k];
                a0.x += u.x * h4.x; a0.y += u.x * h4.y; a0.z += u.x * h4.z; a0.w += u.x * h4.w;
                a1.x += u.y * h4.x; a1.y += u.y * h4.y; a1.z += u.y * h4.z; a1.w += u.y * h4.w;
                a2.x += u.z * h4.x; a2.y += u.z * h4.y; a2.z += u.z * h4.z; a2.w += u.z * h4.w;
                a3.x += u.w * h4.x; a3.y += u.w * h4.y; a3.z += u.w * h4.z; a3.w += u.w * h4.w;
            }
            float4* redq = (float4*)red;
            int base = ((ks * 4 + g) * 4) * 16 + bq;
            redq[base]      = a0;
            redq[base + 16] = a1;
            redq[base + 32] = a2;
            redq[base + 48] = a3;
        }
        __syncthreads();
        if (tid < 256) {
            float pre[4] = {gx0, gx1, gx2, gx3};
            #pragma unroll
            for (int gg = 0; gg < 4; gg++) {
                float v = pre[gg];
                #pragma unroll
                for (int k8 = 0; k8 < 8; k8++)
                    v += red[((k8 * 4 + gg) * 4 + jj) * 64 + b2];
                pre[gg] = v;
            }
            float it = 1.0f / (1.0f + __expf(-pre[0]));
            float ft = 1.0f / (1.0f + __expf(-pre[1]));
            float ot = 1.0f / (1.0f + __expf(-pre[2]));
            float ct = tanhf(pre[3]);
            float cn = ft * s_c[jj][b2] + it * ct;
            s_c[jj][b2] = cn;
            float hn = ot * tanhf(cn);
            g_h[(s + 1) & 1][(j0 + jj) * B_ + b2] = hn;
            hsw[jj * 64 + b2] = hn;
        }
        __syncthreads();
        if (tid < B_) {
            float4 hv = make_float4(hsw[tid], hsw[64 + tid], hsw[128 + tid], hsw[192 + tid]);
            *(float4*)(out + ((size_t)s * B_ + tid) * H_ + j0) = hv;
            if (s == S_ - 1)
                *(float4*)(out + (size_t)S_ * B_ * H_ + (size_t)tid * H_ + j0) = hv;
        }
        if (s < S_ - 1) grid_barrier(phase, NWORK);
    }
}

// =====================================================================
extern "C" void kernel_launch(void* const* d_in, const int* in_sizes, int n_in,
                              void* d_out, int out_size) {
    (void)in_sizes; (void)n_in; (void)out_size;
    const float* x  = (const float*)d_in[0];
    const float* Wi = (const float*)d_in[1], *Wf = (const float*)d_in[2];
    const float* Wo = (const float*)d_in[3], *Wc = (const float*)d_in[4];
    const float* Ui = (const float*)d_in[5], *Uf = (const float*)d_in[6];
    const float* Uo = (const float*)d_in[7], *Uc = (const float*)d_in[8];
    const float* bi = (const float*)d_in[9], *bf = (const float*)d_in[10];
    const float* bo = (const float*)d_in[11], *bc = (const float*)d_in[12];
    float* out = (float*)d_out;

    cudaFuncSetAttribute(gemm_a_kernel, cudaFuncAttributeMaxDynamicSharedMemorySize, SM_TOT);
    cudaFuncSetAttribute(lstm_b_kernel, cudaFuncAttributeMaxDynamicSharedMemorySize, SMEM_B_DYN);

    prep_kernel<<<256, 256>>>(x, Wi, Wf, Wo, Wc, out);
    gemm_a_kernel<<<8192, 256, SM_TOT>>>(bi, bf, bo, bc);
    lstm_b_kernel<<<NWORK, NTB, SMEM_B_DYN>>>(Ui, Uf, Uo, Uc, out);
}